// round 4
// baseline (speedup 1.0000x reference)
#include <cuda_runtime.h>
#include <cuda_bf16.h>

// B=32, C=512, H=W=64
//   d=max_HW x, e=mean_HW x ; y=softmax_j(d_i d_j + e_i e_j)
//   f_j = alpha*sum_i d_i y_ij + beta*sum_i e_i y_ij ; out[b,c,:,:]=f[b,c]
//
// SINGLE persistent kernel, 512 co-resident blocks, device grid barriers:
//   A: pool (read 268MB) -> bar -> B1: rowsum -> bar -> B2: colsum->f
//   -> bar -> C: broadcast (write 268MB)
// Residency proof: launch_bounds(256,4) caps regs at 64; smem 4.2KB/block;
// 4 blocks/SM = 1024 thr + 17KB smem + <=64 regs -> fits; 512/4 = 128 SMs
// <= 148 -> all blocks co-resident in wave 1, barriers cannot deadlock.
// No max-subtract: |logit| <= d_max^2 ~ 18 << 88 (exp finite in fp32).

#define BATCH 32
#define CH    512
#define HW    4096
#define BC    (BATCH * CH)
#define NB    512
#define NT    256
#define TILES_PER_BLK (BC / NB)   // 32

__device__ float    g_d[BC];
__device__ float    g_e[BC];
__device__ float4   g_pack[BC];   // (d_i, e_i, alpha*d_i/s_i, beta*e_i/s_i)
__device__ float    g_f[BC];
__device__ unsigned g_ctr[3];     // zero-init; reset by last arriver each launch
__device__ unsigned g_rel[3];     // monotonic generation counters

__device__ __forceinline__ unsigned ld_vol(const unsigned* p) {
    return *(volatile const unsigned*)p;
}

// Grid barrier, safe across graph replays: caller passes the g_rel[k] value
// snapshotted at block start (before this block's first arrival -> provably
// before any release of barrier k in this launch).
__device__ __forceinline__ void gbar(int k, unsigned base) {
    __syncthreads();
    if (threadIdx.x == 0) {
        __threadfence();
        if (atomicAdd(&g_ctr[k], 1u) == NB - 1u) {
            g_ctr[k] = 0;                 // never read again this launch
            __threadfence();
            atomicAdd(&g_rel[k], 1u);
        }
        while (ld_vol(&g_rel[k]) == base) __nanosleep(32);
        __threadfence();
    }
    __syncthreads();
}

struct SmemT {
    union {
        float2 de[CH];     // phase B1
        float4 pk[CH];     // phase B2
    };
    float redmx[8];
    float redsm[8];
};

__global__ void __launch_bounds__(NT, 4)
fused_kernel(const float4* __restrict__ x, float4* __restrict__ out,
             const float* __restrict__ alpha, const float* __restrict__ beta) {
    __shared__ SmemT s;
    const int t   = threadIdx.x;
    const int blk = blockIdx.x;
    const int w   = t >> 5;
    const int ln  = t & 31;

    // Snapshot barrier generations BEFORE any arrival.
    unsigned b0 = 0, b1 = 0, b2 = 0;
    if (t == 0) { b0 = ld_vol(&g_rel[0]); b1 = ld_vol(&g_rel[1]); b2 = ld_vol(&g_rel[2]); }

    // ---------------- Phase A: pool. Tiles it*NB + blk, double-buffered. ----
    {
        const float4* p0 = x + (size_t)blk * (HW / 4);
        float4 v0 = __ldcs(p0 + t);
        float4 v1 = __ldcs(p0 + t + 256);
        float4 v2 = __ldcs(p0 + t + 512);
        float4 v3 = __ldcs(p0 + t + 768);

        for (int it = 0; it < TILES_PER_BLK; ++it) {
            float4 w0, w1, w2, w3;
            if (it + 1 < TILES_PER_BLK) {
                const float4* pn = x + (size_t)((it + 1) * NB + blk) * (HW / 4);
                w0 = __ldcs(pn + t);
                w1 = __ldcs(pn + t + 256);
                w2 = __ldcs(pn + t + 512);
                w3 = __ldcs(pn + t + 768);
            }
            float mxa = fmaxf(fmaxf(v0.x, v0.y), fmaxf(v0.z, v0.w));
            float mxb = fmaxf(fmaxf(v1.x, v1.y), fmaxf(v1.z, v1.w));
            mxa = fmaxf(mxa, fmaxf(fmaxf(v2.x, v2.y), fmaxf(v2.z, v2.w)));
            mxb = fmaxf(mxb, fmaxf(fmaxf(v3.x, v3.y), fmaxf(v3.z, v3.w)));
            float sma = ((v0.x + v0.y) + (v0.z + v0.w)) + ((v2.x + v2.y) + (v2.z + v2.w));
            float smb = ((v1.x + v1.y) + (v1.z + v1.w)) + ((v3.x + v3.y) + (v3.z + v3.w));
            float mx = fmaxf(mxa, mxb);
            float sm = sma + smb;
#pragma unroll
            for (int o = 16; o > 0; o >>= 1) {
                mx = fmaxf(mx, __shfl_xor_sync(0xFFFFFFFFu, mx, o));
                sm += __shfl_xor_sync(0xFFFFFFFFu, sm, o);
            }
            if (ln == 0) { s.redmx[w] = mx; s.redsm[w] = sm; }
            __syncthreads();
            if (t < 8) {
                mx = s.redmx[t];
                sm = s.redsm[t];
#pragma unroll
                for (int o = 4; o > 0; o >>= 1) {
                    mx = fmaxf(mx, __shfl_xor_sync(0x000000FFu, mx, o));
                    sm += __shfl_xor_sync(0x000000FFu, sm, o);
                }
                if (t == 0) {
                    const int bc = it * NB + blk;
                    g_d[bc] = mx;
                    g_e[bc] = sm * (1.0f / HW);
                }
            }
            __syncthreads();
            v0 = w0; v1 = w1; v2 = w2; v3 = w3;
        }
    }
    gbar(0, b0);

    // ---------------- Phase B1: row sums (blocks 0..63). --------------------
    if (blk < 2 * BATCH) {
        const int b  = blk >> 1;
        const int i0 = (blk & 1) * 256;
        const float al = __ldg(alpha);
        const float be = __ldg(beta);
        for (int k = t; k < CH; k += NT)
            s.de[k] = make_float2(__ldcg(&g_d[b * CH + k]), __ldcg(&g_e[b * CH + k]));
        __syncthreads();

        const int i  = i0 + t;
        const float di = s.de[i].x;
        const float ei = s.de[i].y;
        float ssum = 0.0f;
#pragma unroll 8
        for (int j = 0; j < CH; ++j) {
            float2 v = s.de[j];
            ssum += __expf(fmaf(di, v.x, ei * v.y));
        }
        const float inv = 1.0f / ssum;
        g_pack[b * CH + i] = make_float4(di, ei, al * di * inv, be * ei * inv);
    }
    gbar(1, b1);

    // ---------------- Phase B2: col sums -> f (blocks 0..63). ---------------
    if (blk < 2 * BATCH) {
        const int b  = blk >> 1;
        const int j0 = (blk & 1) * 256;
        for (int k = t; k < CH; k += NT)
            s.pk[k] = __ldcg(&g_pack[b * CH + k]);
        __syncthreads();

        const int j  = j0 + t;
        const float dj = s.pk[j].x;
        const float ej = s.pk[j].y;
        float fm = 0.0f, fe = 0.0f;
#pragma unroll 8
        for (int i = 0; i < CH; ++i) {
            float4 v = s.pk[i];
            float E = __expf(fmaf(dj, v.x, ej * v.y));
            fm = fmaf(v.z, E, fm);
            fe = fmaf(v.w, E, fe);
        }
        g_f[b * CH + j] = fm + fe;
    }
    gbar(2, b2);

    // ---------------- Phase C: broadcast (write 268 MB). --------------------
    for (int it = 0; it < TILES_PER_BLK; ++it) {
        const int bc = it * NB + blk;
        const float v = __ldcg(&g_f[bc]);
        const float4 vv = make_float4(v, v, v, v);
        float4* p = out + (size_t)bc * (HW / 4);
        __stcs(p + t,       vv);
        __stcs(p + t + 256, vv);
        __stcs(p + t + 512, vv);
        __stcs(p + t + 768, vv);
    }
}

extern "C" void kernel_launch(void* const* d_in, const int* in_sizes, int n_in,
                              void* d_out, int out_size) {
    const float* x     = (const float*)d_in[0];
    const float* alpha = (const float*)d_in[1];
    const float* beta  = (const float*)d_in[2];
    float* out = (float*)d_out;

    fused_kernel<<<NB, NT>>>((const float4*)x, (float4*)out, alpha, beta);
}

// round 5
// speedup vs baseline: 1.0520x; 1.0520x over previous
#include <cuda_runtime.h>
#include <cuda_bf16.h>

// B=32, C=512, H=W=64
//   d=max_HW x, e=mean_HW x ; y=softmax_j(d_i d_j + e_i e_j)
//   f_j = alpha*sum_i d_i y_ij + beta*sum_i e_i y_ij ; out[b,c,:,:]=f[b,c]
//
// SINGLE persistent kernel, 888 co-resident blocks (148 SMs x 6), grid barriers:
//   A: pool (read 268MB, warp-per-tile, no block syncs)
//   -> bar -> B1: rowsum -> bar -> B2: colsum->f -> bar ->
//   C: broadcast (write 268MB, warp-per-tile)
// Residency proof: launch_bounds(256,6) caps regs at 40; smem 8.3KB/block ->
// 6 blocks/SM = 1536 thr + 50KB smem, fits; 888/6 = 148 SMs -> all blocks
// co-resident in wave 1, barriers cannot deadlock.
// No max-subtract: |logit| <= d_max^2 ~ 18 << 88 (exp finite in fp32).

#define BATCH 32
#define CH    512
#define HW    4096
#define BC    (BATCH * CH)
#define NB    888
#define NT    256
#define NWARP (NB * (NT / 32))    // 7104 warps

__device__ float    g_d[BC];
__device__ float    g_e[BC];
__device__ float4   g_pack[BC];   // (d_i, e_i, alpha*d_i/s_i, beta*e_i/s_i)
__device__ float    g_f[BC];
__device__ unsigned g_ctr[3];     // zero-init; reset by last arriver each launch
__device__ unsigned g_rel[3];     // monotonic generation counters

__device__ __forceinline__ unsigned ld_vol(const unsigned* p) {
    return *(volatile const unsigned*)p;
}

// Grid barrier, safe across graph replays: base = g_rel[k] snapshotted at
// block start (provably before any release of barrier k in this launch).
__device__ __forceinline__ void gbar(int k, unsigned base) {
    __syncthreads();
    if (threadIdx.x == 0) {
        __threadfence();
        if (atomicAdd(&g_ctr[k], 1u) == NB - 1u) {
            g_ctr[k] = 0;                 // never read again this launch
            __threadfence();
            atomicAdd(&g_rel[k], 1u);
        }
        while (ld_vol(&g_rel[k]) == base) __nanosleep(32);
        __threadfence();
    }
    __syncthreads();
}

struct SmemT {
    union {
        float2 de[CH];     // phase B1 (4KB)
        float4 pk[CH];     // phase B2 (8KB)
    };
};

__global__ void __launch_bounds__(NT, 6)
fused_kernel(const float4* __restrict__ x, float4* __restrict__ out,
             const float* __restrict__ alpha, const float* __restrict__ beta) {
    __shared__ SmemT s;
    const int t   = threadIdx.x;
    const int blk = blockIdx.x;
    const int w   = t >> 5;
    const int ln  = t & 31;
    const int gw  = blk * (NT / 32) + w;   // global warp id

    // Snapshot barrier generations BEFORE any arrival.
    unsigned b0 = 0, b1 = 0, b2 = 0;
    if (t == 0) { b0 = ld_vol(&g_rel[0]); b1 = ld_vol(&g_rel[1]); b2 = ld_vol(&g_rel[2]); }

    // ---------------- Phase A: pool, warp-per-tile (no block syncs). --------
    for (int tile = gw; tile < BC; tile += NWARP) {
        const float4* p = x + (size_t)tile * (HW / 4);
        float mx0 = -3.402823466e38f, mx1 = mx0;
        float sm0 = 0.0f, sm1 = 0.0f;
#pragma unroll 4
        for (int k = 0; k < HW / 4 / 32; ++k) {        // 32 iters
            float4 v = __ldcs(p + ln + 32 * k);
            float m = fmaxf(fmaxf(v.x, v.y), fmaxf(v.z, v.w));
            float a = (v.x + v.y) + (v.z + v.w);
            if (k & 1) { mx1 = fmaxf(mx1, m); sm1 += a; }
            else       { mx0 = fmaxf(mx0, m); sm0 += a; }
        }
        float mx = fmaxf(mx0, mx1);
        float sm = sm0 + sm1;
#pragma unroll
        for (int o = 16; o > 0; o >>= 1) {
            mx = fmaxf(mx, __shfl_xor_sync(0xFFFFFFFFu, mx, o));
            sm += __shfl_xor_sync(0xFFFFFFFFu, sm, o);
        }
        if (ln == 0) {
            g_d[tile] = mx;
            g_e[tile] = sm * (1.0f / HW);
        }
    }
    gbar(0, b0);

    // ---------------- Phase B1: row sums (blocks 0..63). --------------------
    if (blk < 2 * BATCH) {
        const int b  = blk >> 1;
        const int i0 = (blk & 1) * 256;
        const float al = __ldg(alpha);
        const float be = __ldg(beta);
        for (int k = t; k < CH; k += NT)
            s.de[k] = make_float2(__ldcg(&g_d[b * CH + k]), __ldcg(&g_e[b * CH + k]));
        __syncthreads();

        const int i  = i0 + t;
        const float di = s.de[i].x;
        const float ei = s.de[i].y;
        float ssum = 0.0f;
#pragma unroll 8
        for (int j = 0; j < CH; ++j) {
            float2 v = s.de[j];
            ssum += __expf(fmaf(di, v.x, ei * v.y));
        }
        const float inv = 1.0f / ssum;
        g_pack[b * CH + i] = make_float4(di, ei, al * di * inv, be * ei * inv);
    }
    gbar(1, b1);

    // ---------------- Phase B2: col sums -> f (blocks 0..63). ---------------
    if (blk < 2 * BATCH) {
        const int b  = blk >> 1;
        const int j0 = (blk & 1) * 256;
        for (int k = t; k < CH; k += NT)
            s.pk[k] = __ldcg(&g_pack[b * CH + k]);
        __syncthreads();

        const int j  = j0 + t;
        const float dj = s.pk[j].x;
        const float ej = s.pk[j].y;
        float fm = 0.0f, fe = 0.0f;
#pragma unroll 8
        for (int i = 0; i < CH; ++i) {
            float4 v = s.pk[i];
            float E = __expf(fmaf(dj, v.x, ej * v.y));
            fm = fmaf(v.z, E, fm);
            fe = fmaf(v.w, E, fe);
        }
        g_f[b * CH + j] = fm + fe;
    }
    gbar(2, b2);

    // ---------------- Phase C: broadcast, warp-per-tile (write 268 MB). -----
    for (int tile = gw; tile < BC; tile += NWARP) {
        const float v = __ldcg(&g_f[tile]);
        const float4 vv = make_float4(v, v, v, v);
        float4* p = out + (size_t)tile * (HW / 4);
#pragma unroll 4
        for (int k = 0; k < HW / 4 / 32; ++k)
            p[ln + 32 * k] = vv;
    }
}

extern "C" void kernel_launch(void* const* d_in, const int* in_sizes, int n_in,
                              void* d_out, int out_size) {
    const float* x     = (const float*)d_in[0];
    const float* alpha = (const float*)d_in[1];
    const float* beta  = (const float*)d_in[2];
    float* out = (float*)d_out;

    fused_kernel<<<NB, NT>>>((const float4*)x, (float4*)out, alpha, beta);
}